// round 15
// baseline (speedup 1.0000x reference)
#include <cuda_runtime.h>

#define NN 10
#define MM 22
#define RR 2
#define NPAIR 55
#define TPB 384     // 12 warps = 3 groups x 4 warps; each group: 55 pairs x 2 halves in lanes
#define BPB 32      // batches per block; groups take 10/11/11

typedef unsigned long long u64;

__device__ ulonglong2 gcoef[NPAIR][MM];   // packed (A_r0,A_r1 | B_r0,B_r1), alpha folded at m==0

__constant__ int PAIR_CELL[NPAIR] = {
  0,1,2,3,4,5,6,7,8,9,
  11,12,13,14,15,16,17,18,19,
  22,23,24,25,26,27,28,29,
  33,34,35,36,37,38,39,
  44,45,46,47,48,49,
  55,56,57,58,59,
  66,67,68,69,
  77,78,79,
  88,89,
  99};

__device__ __forceinline__ u64 pack2(float x, float y) {
    u64 r; asm("mov.b64 %0, {%1, %2};" : "=l"(r) : "f"(x), "f"(y)); return r;
}
__device__ __forceinline__ void unpack2(u64 v, float& x, float& y) {
    asm("mov.b64 {%0, %1}, %2;" : "=f"(x), "=f"(y) : "l"(v));
}
__device__ __forceinline__ u64 fma2(u64 a, u64 b, u64 c) {
    u64 d; asm("fma.rn.f32x2 %0, %1, %2, %3;" : "=l"(d) : "l"(a), "l"(b), "l"(c)); return d;
}
__device__ __forceinline__ u64 mul2(u64 a, u64 b) {
    u64 d; asm("mul.rn.f32x2 %0, %1, %2;" : "=l"(d) : "l"(a), "l"(b)); return d;
}
__device__ __forceinline__ u64 one2() { return 0x3f8000003f800000ULL; }

// ---- One-shot coefficient build: softmax over literal selectors + alpha fold ----
__global__ void tl_build(const float* __restrict__ sel, const float* __restrict__ alog) {
    int idx = blockIdx.x * blockDim.x + threadIdx.x;
    if (idx >= NPAIR * MM) return;
    int p = idx / MM, m = idx - p * MM;
    int i = 0, rem = p;
    while (rem >= NN - i) { rem -= NN - i; i++; }
    int j = i + rem;
    float Av[RR], Bv[RR];
#pragma unroll
    for (int r = 0; r < RR; r++) {
        const float* s = sel + (size_t)((((i * NN + j) * RR + r) * MM + m) * 3);
        float x0 = s[0] * 1.25f, x1 = s[1] * 1.25f, x2 = s[2] * 1.25f;  // /LIT_TEMP
        float mx = fmaxf(x0, fmaxf(x1, x2));
        float e0 = __expf(x0 - mx), e1 = __expf(x1 - mx), e2 = __expf(x2 - mx);
        float inv = 1.0f / (e0 + e1 + e2);
        float s0 = e0 * inv, s1 = e1 * inv, s2 = e2 * inv;
        float A = s0 + s2, Bc = s1 - s2;       // lit = A + B*u
        if (m == 0) {                           // fold alpha = sigmoid(alog)
            float a = alog[(i * NN + j) * RR + r];
            float alpha = 1.0f / (1.0f + __expf(-a));
            A *= alpha; Bc *= alpha;
        }
        Av[r] = A; Bv[r] = Bc;
    }
    ulonglong2 v;
    v.x = pack2(Av[0], Av[1]);
    v.y = pack2(Bv[0], Bv[1]);
    gcoef[p][m] = v;
}

// ---- Main kernel: pairs live in lanes, coefficients live in registers ----
__global__ void __launch_bounds__(TPB, 3)
tl_main(const float* __restrict__ pred,   // (B, M)
        float* __restrict__ out,          // (B, N, N)
        int B) {
    __shared__ ulonglong2 shl[NPAIR * MM]; // 19.4 KB linear coef stage
    __shared__ u64   psm2[BPB][24];        // 6.1 KB (u,u) splats; halves at slots 0..10 / 12..22
    __shared__ float wtile[BPB][101];      // 12.9 KB raw w tile (pad 101)
    __shared__ float rinvt[BPB][11];       // 1.4 KB per-(batch,row) 1/rowsum

    // Stage coefficients linearly: LDG.128 coalesced, STS.128 consecutive (no conflicts)
    {
        const ulonglong2* gsrc = &gcoef[0][0];
        for (int t = threadIdx.x; t < NPAIR * MM; t += TPB) shl[t] = gsrc[t];
    }
    // Stage this block's 32x22 pred slab; slot = m + (m>=11) so each half is 16B-aligned
    {
        const float* gp = pred + (size_t)blockIdx.x * BPB * MM;
        int nelem = BPB * MM;
        long gmax = (long)B * MM - (long)blockIdx.x * BPB * MM;
        if (nelem > gmax) nelem = (int)gmax;
        for (int t = threadIdx.x; t < nelem; t += TPB) {
            int bb = t / MM, m = t - bb * MM;
            float v = __ldg(gp + t);
            psm2[bb][m + (m >= 11 ? 1 : 0)] = pack2(v, v);
        }
    }

    const int lane  = threadIdx.x & 31;
    const int w     = threadIdx.x >> 5;          // warp 0..11
    const int group = w >> 2;                    // 0, 1, 2
    const int gl    = ((w & 3) << 5) + lane;     // lane id within 4-warp group: 0..127
    const int pair  = gl >> 1;                   // 0..63 (55..63 inactive)
    const int half  = gl & 1;                    // which 11-m half
    const int pr    = pair < NPAIR ? pair : NPAIR - 1;   // clamp for safe loads
    const int m0    = half * 11;                 // real m base
    const int s0    = half * 12;                 // slot base in psm2 (16B aligned)

    const bool writer = (half == 0) && (pair < NPAIR);
    const int  cell   = PAIR_CELL[pr];

    __syncthreads();

    // Lane's coefficients smem -> registers (lane stride 11 units, odd -> conflict-free)
    ulonglong2 cf[11];
#pragma unroll
    for (int k = 0; k < 11; k++) cf[k] = shl[pr * MM + m0 + k];

    // ---- Phase 1: group handles ~1/3 of the batches; lane computes its half-pair ----
    int bmax = B - blockIdx.x * BPB;
    if (bmax > BPB) bmax = BPB;
    int b0 = (group * BPB) / 3;                  // 0, 10, 21
    int b1 = ((group + 1) * BPB) / 3;            // 10, 21, 32
    if (b1 > bmax) b1 = bmax;

#pragma unroll 2
    for (int b = b0; b < b1; b++) {
        const ulonglong2* upv = reinterpret_cast<const ulonglong2*>(&psm2[b][s0]);
        u64 accA = one2(), accB = one2();        // two chains for ILP
#pragma unroll
        for (int j = 0; j < 5; j++) {            // 5 x LDS.128: u pairs (2j, 2j+1)
            ulonglong2 uv = upv[j];
            accA = mul2(accA, fma2(cf[2 * j].y,     uv.x, cf[2 * j].x));     // lit=B*u+A
            accB = mul2(accB, fma2(cf[2 * j + 1].y, uv.y, cf[2 * j + 1].x));
        }
        accA = mul2(accA, fma2(cf[10].y, psm2[b][s0 + 10], cf[10].x));       // last m (LDS.64)
        u64 mine = mul2(accA, accB);             // product over this lane's 11 m's
        u64 both = mul2(mine, __shfl_xor_sync(0xffffffffu, mine, 1));  // x partner half
        float c0f, c1f;
        unpack2(both, c0f, c1f);                 // c_r = alpha_r * clause_r
        float gg = c0f + c1f - c0f * c1f;        // 1 - (1-c0)(1-c1)
        float gc = fmaxf(gg, 1e-6f);
        if (writer) wtile[b][cell] = gc * gc;    // exp(log(g)/0.5) == g^2
    }
    __syncthreads();

    // ---- Phase 2: row sums -> 1/rowsum (320 (batch,row) cells, strided) ----
#pragma unroll 1
    for (int t = threadIdx.x; t < BPB * NN; t += TPB) {
        int bb = t & 31, row = t >> 5;
        const float* cells = &wtile[bb][row * NN];
        float s = 0.0f;
#pragma unroll 1
        for (int j = row; j < NN; j++) s += cells[j];
        rinvt[bb][row] = 1.0f / s;
    }
    __syncthreads();

    // ---- Phase 3: coalesced, normalized write-out with lower-triangle zeros ----
    int emax = bmax * (NN * NN);
    float* ob = out + (size_t)blockIdx.x * (BPB * NN * NN);
#pragma unroll 1
    for (int e = threadIdx.x; e < emax; e += TPB) {
        int bb  = e / 100, c = e - bb * 100;
        int row = c / 10,  col = c - row * 10;
        float v = (col >= row) ? wtile[bb][c] * rinvt[bb][row] : 0.0f;
        ob[e] = v;
    }
}

extern "C" void kernel_launch(void* const* d_in, const int* in_sizes, int n_in,
                              void* d_out, int out_size) {
    const float* pred = (const float*)d_in[0];   // (B, M)
    const float* sel  = (const float*)d_in[1];   // (N, N, R, M, 3)
    const float* alog = (const float*)d_in[2];   // (N, N, R)
    float* out = (float*)d_out;                  // (B, N, N)
    int B = in_sizes[0] / MM;
    tl_build<<<10, 128>>>(sel, alog);            // 1210 entries, one-shot
    int blocks = (B + BPB - 1) / BPB;            // 512 blocks of 384 threads, 3 blocks/SM
    tl_main<<<blocks, TPB>>>(pred, out, B);
}

// round 16
// speedup vs baseline: 1.1779x; 1.1779x over previous
#include <cuda_runtime.h>

#define NN 10
#define MM 22
#define RR 2
#define NPAIR 55
#define TPB 256     // 8 warps; warp w owns pairs [w*7, w*7+7) (warp 7: 6 pairs)
#define BPB 32      // one batch per lane

typedef unsigned long long u64;

__device__ ulonglong2 gcoef[NPAIR][MM];   // packed (A_r0,A_r1 | B_r0,B_r1), alpha folded at m==0

__constant__ int PAIR_CELL[NPAIR] = {
  0,1,2,3,4,5,6,7,8,9,
  11,12,13,14,15,16,17,18,19,
  22,23,24,25,26,27,28,29,
  33,34,35,36,37,38,39,
  44,45,46,47,48,49,
  55,56,57,58,59,
  66,67,68,69,
  77,78,79,
  88,89,
  99};

__device__ __forceinline__ u64 pack2(float x, float y) {
    u64 r; asm("mov.b64 %0, {%1, %2};" : "=l"(r) : "f"(x), "f"(y)); return r;
}
__device__ __forceinline__ void unpack2(u64 v, float& x, float& y) {
    asm("mov.b64 {%0, %1}, %2;" : "=f"(x), "=f"(y) : "l"(v));
}
__device__ __forceinline__ u64 fma2(u64 a, u64 b, u64 c) {
    u64 d; asm("fma.rn.f32x2 %0, %1, %2, %3;" : "=l"(d) : "l"(a), "l"(b), "l"(c)); return d;
}
__device__ __forceinline__ u64 mul2(u64 a, u64 b) {
    u64 d; asm("mul.rn.f32x2 %0, %1, %2;" : "=l"(d) : "l"(a), "l"(b)); return d;
}
__device__ __forceinline__ u64 one2() { return 0x3f8000003f800000ULL; }

// Evaluate one clause-pair: w = clamp(1-(1-c0)(1-c1), 1e-6)^2, fully unrolled.
__device__ __forceinline__ float clause_w(const ulonglong2* __restrict__ cp,
                                          const u64* __restrict__ u2) {
    u64 accA = one2(), accB = one2();          // even/odd m chains
#pragma unroll
    for (int m = 0; m < MM; m += 2) {
        ulonglong2 c0 = cp[m];
        ulonglong2 c1 = cp[m + 1];
        accA = mul2(accA, fma2(c0.y, u2[m],     c0.x));   // lit = B*u + A (both r)
        accB = mul2(accB, fma2(c1.y, u2[m + 1], c1.x));
    }
    float c0f, c1f;
    unpack2(mul2(accA, accB), c0f, c1f);       // c_r = alpha_r * clause_r
    float gg = c0f + c1f - c0f * c1f;          // 1 - (1-c0)(1-c1)
    float gc = fmaxf(gg, 1e-6f);
    return gc * gc;                            // exp(log(g)/0.5) == g^2
}

// ---- One-shot coefficient build: softmax over literal selectors + alpha fold ----
__global__ void tl_build(const float* __restrict__ sel, const float* __restrict__ alog) {
    int idx = blockIdx.x * blockDim.x + threadIdx.x;
    if (idx >= NPAIR * MM) return;
    int p = idx / MM, m = idx - p * MM;
    int i = 0, rem = p;
    while (rem >= NN - i) { rem -= NN - i; i++; }
    int j = i + rem;
    float Av[RR], Bv[RR];
#pragma unroll
    for (int r = 0; r < RR; r++) {
        const float* s = sel + (size_t)((((i * NN + j) * RR + r) * MM + m) * 3);
        float x0 = s[0] * 1.25f, x1 = s[1] * 1.25f, x2 = s[2] * 1.25f;  // /LIT_TEMP
        float mx = fmaxf(x0, fmaxf(x1, x2));
        float e0 = __expf(x0 - mx), e1 = __expf(x1 - mx), e2 = __expf(x2 - mx);
        float inv = 1.0f / (e0 + e1 + e2);
        float s0 = e0 * inv, s1 = e1 * inv, s2 = e2 * inv;
        float A = s0 + s2, Bc = s1 - s2;       // lit = A + B*u
        if (m == 0) {                           // fold alpha = sigmoid(alog)
            float a = alog[(i * NN + j) * RR + r];
            float alpha = 1.0f / (1.0f + __expf(-a));
            A *= alpha; Bc *= alpha;
        }
        Av[r] = A; Bv[r] = Bc;
    }
    ulonglong2 v;
    v.x = pack2(Av[0], Av[1]);
    v.y = pack2(Bv[0], Bv[1]);
    gcoef[p][m] = v;
}

// ---- Main kernel ----
__global__ void __launch_bounds__(TPB, 4)
tl_main(const float* __restrict__ pred,   // (B, M)
        float* __restrict__ out,          // (B, N, N)
        int B) {
    __shared__ ulonglong2 sh[NPAIR][MM];   // 19.4 KB coefficients
    __shared__ float wtile[BPB][101];      // 12.9 KB raw w tile (pad 101: conflict-free)
    __shared__ float rinvt[BPB][11];       // 1.4 KB per-(batch,row) 1/rowsum
    __shared__ float psm[BPB][MM + 1];     // 2.9 KB staged pred (pad 23: conflict-free)

    // Coefficient table gmem -> smem (coalesced LDG.128 / STS.128)
    {
        const ulonglong2* gsrc = &gcoef[0][0];
        ulonglong2* sdst = &sh[0][0];
        for (int idx = threadIdx.x; idx < NPAIR * MM; idx += TPB) sdst[idx] = gsrc[idx];
    }
    // Stage this block's 32x22 pred slab, coalesced
    {
        const float* gp = pred + (size_t)blockIdx.x * BPB * MM;
        int nelem = BPB * MM;
        long gmax = (long)B * MM - (long)blockIdx.x * BPB * MM;
        if (nelem > gmax) nelem = (int)gmax;
        for (int t = threadIdx.x; t < nelem; t += TPB) {
            int bb = t / MM, m = t - bb * MM;
            psm[bb][m] = __ldg(gp + t);
        }
    }
    __syncthreads();

    const int lane = threadIdx.x & 31;
    const int w    = threadIdx.x >> 5;           // warp 0..7

    // u from smem, duplicated into packed f32x2 regs (stride 23: conflict-free)
    u64 u2[MM];
#pragma unroll
    for (int m = 0; m < MM; m++) {
        float v = psm[lane][m];
        u2[m] = pack2(v, v);
    }

    // ---- Phase 1: warp w owns 7 pairs (warp 7: 6). 3 double-iters + 1 guarded. ----
    {
        const int p0 = w * 7;
        float* wrow = wtile[lane];
#pragma unroll 1
        for (int d = 0; d < 3; d++) {
            int p = p0 + 2 * d;
            // two independent clause evaluations -> 4 acc chains interleaved by ptxas
            float w0 = clause_w(sh[p],     u2);
            float w1 = clause_w(sh[p + 1], u2);
            wrow[PAIR_CELL[p]]     = w0;
            wrow[PAIR_CELL[p + 1]] = w1;
        }
        if (w < 7) {
            int p = p0 + 6;
            wrow[PAIR_CELL[p]] = clause_w(sh[p], u2);
        }
    }
    __syncthreads();

    // ---- Phase 2: row sums -> 1/rowsum (320 (batch,row) cells, strided) ----
#pragma unroll 1
    for (int t = threadIdx.x; t < BPB * NN; t += TPB) {
        int bb = t & 31, row = t >> 5;
        const float* cells = &wtile[bb][row * NN];
        float s = 0.0f;
#pragma unroll 1
        for (int j = row; j < NN; j++) s += cells[j];
        rinvt[bb][row] = 1.0f / s;
    }
    __syncthreads();

    // ---- Phase 3: coalesced, normalized write-out with lower-triangle zeros ----
    int bmax = B - blockIdx.x * BPB;
    if (bmax > BPB) bmax = BPB;
    int emax = bmax * (NN * NN);
    float* ob = out + (size_t)blockIdx.x * (BPB * NN * NN);
#pragma unroll 1
    for (int e = threadIdx.x; e < emax; e += TPB) {
        int bb  = e / 100, c = e - bb * 100;
        int row = c / 10,  col = c - row * 10;
        float v = (col >= row) ? wtile[bb][c] * rinvt[bb][row] : 0.0f;
        ob[e] = v;
    }
}

extern "C" void kernel_launch(void* const* d_in, const int* in_sizes, int n_in,
                              void* d_out, int out_size) {
    const float* pred = (const float*)d_in[0];   // (B, M)
    const float* sel  = (const float*)d_in[1];   // (N, N, R, M, 3)
    const float* alog = (const float*)d_in[2];   // (N, N, R)
    float* out = (float*)d_out;                  // (B, N, N)
    int B = in_sizes[0] / MM;
    tl_build<<<10, 128>>>(sel, alog);            // 1210 entries, one-shot
    int blocks = (B + BPB - 1) / BPB;            // 512 blocks, 4 blocks/SM
    tl_main<<<blocks, TPB>>>(pred, out, B);
}